// round 13
// baseline (speedup 1.0000x reference)
#include <cuda_runtime.h>
#include <cuda_fp16.h>
#include <math.h>
#include <stdint.h>

#define B 4096
#define LATENT 512
#define H 8
#define D 64
#define KVB_N (H * (2 * D + 1))   // 1032

// ---------------- scratch (device globals; no allocation allowed) -----------
__device__ float g_h[B * LATENT];                 // post-GEMM1 / post-LN (fp32)
__device__ float g_h2[B * LATENT];                // post-GEMM2 (fp32)
__device__ float g_kvb[B * KVB_N];                // post-GEMM3 (fp32)
__device__ __half g_ipwT[512 * 512];              // [N=512,K=512]  fp16
__device__ __half g_mgwT[512 * 1024];             // [N=512,K=1024] fp16
__device__ __half g_kvbwT[KVB_N * 512];           // [N=1032,K=512] fp16

// ---------------- helpers ----------------------------------------------------
__device__ __forceinline__ uint32_t smem_u32(const void* p) {
    uint32_t a;
    asm("{ .reg .u64 t; cvta.to.shared.u64 t, %1; cvt.u32.u64 %0, t; }"
        : "=r"(a) : "l"(p));
    return a;
}
__device__ __forceinline__ void ldm_x4(uint32_t (&r)[4], uint32_t addr) {
    asm volatile("ldmatrix.sync.aligned.m8n8.x4.shared.b16 {%0,%1,%2,%3}, [%4];"
        : "=r"(r[0]), "=r"(r[1]), "=r"(r[2]), "=r"(r[3]) : "r"(addr));
}
// non-volatile: pure register op, lets ptxas schedule/pipeline HMMAs.
__device__ __forceinline__ void mma16816h(float* c, const uint32_t* a,
                                          uint32_t b0, uint32_t b1) {
    asm("mma.sync.aligned.m16n8k16.row.col.f32.f16.f16.f32 "
        "{%0,%1,%2,%3}, {%4,%5,%6,%7}, {%8,%9}, {%0,%1,%2,%3};"
        : "+f"(c[0]), "+f"(c[1]), "+f"(c[2]), "+f"(c[3])
        : "r"(a[0]), "r"(a[1]), "r"(a[2]), "r"(a[3]), "r"(b0), "r"(b1));
}
__device__ __forceinline__ void cpasync16(uint32_t dst, const void* src) {
    asm volatile("cp.async.ca.shared.global [%0], [%1], 16;"
                 :: "r"(dst), "l"(src) : "memory");
}
// convert 8 fp32 -> 8 fp16, packed uint4
__device__ __forceinline__ uint4 cvt8h(const float4& a, const float4& b) {
    __half2 p0 = __floats2half2_rn(a.x, a.y);
    __half2 p1 = __floats2half2_rn(a.z, a.w);
    __half2 p2 = __floats2half2_rn(b.x, b.y);
    __half2 p3 = __floats2half2_rn(b.z, b.w);
    uint4 r;
    r.x = *(uint32_t*)&p0; r.y = *(uint32_t*)&p1;
    r.z = *(uint32_t*)&p2; r.w = *(uint32_t*)&p3;
    return r;
}

// ---------------- weight transpose+convert (64x64 tiles) --------------------
// src [K,N] fp32 -> dst [N,K] fp16
__global__ __launch_bounds__(256) void tcvt_tiled(
    const float* __restrict__ src, __half* __restrict__ dst, int K, int N)
{
    __shared__ __half th[64][72];
    int k0 = blockIdx.x * 64, n0 = blockIdx.y * 64;
    int t = threadIdx.x;
    {
        int r  = t >> 2;             // 0..63 (k within tile)
        int c0 = (t & 3) * 16;       // n within tile
        const float* sp = src + (size_t)(k0 + r) * N + n0 + c0;
        #pragma unroll
        for (int j = 0; j < 4; j++) {
            int gn = n0 + c0 + j * 4;
            float4 v = make_float4(0.f, 0.f, 0.f, 0.f);
            if (gn + 3 < N) {
                v = *(const float4*)(sp + j * 4);
            } else {
                if (gn + 0 < N) v.x = sp[j * 4 + 0];
                if (gn + 1 < N) v.y = sp[j * 4 + 1];
                if (gn + 2 < N) v.z = sp[j * 4 + 2];
                if (gn + 3 < N) v.w = sp[j * 4 + 3];
            }
            int c = c0 + j * 4;
            th[r][c + 0] = __float2half_rn(v.x);
            th[r][c + 1] = __float2half_rn(v.y);
            th[r][c + 2] = __float2half_rn(v.z);
            th[r][c + 3] = __float2half_rn(v.w);
        }
    }
    __syncthreads();
    {
        int n  = t >> 2;             // n within tile
        int kc = (t & 3) * 16;       // k within tile
        int gn = n0 + n;
        if (gn < N) {
            __half hb[16];
            #pragma unroll
            for (int j = 0; j < 16; j++) hb[j] = th[kc + j][n];
            uint4* hd = (uint4*)(dst + (size_t)gn * K + k0 + kc);
            hd[0] = *(uint4*)&hb[0];
            hd[1] = *(uint4*)&hb[8];
        }
    }
}

// ---------------- pipelined mma.sync GEMM (plain fp16, BK=64) ----------------
// C = A @ Bw^T + bias; A fp32 -> fp16 on stage; Bw fp16.
// 128x64 block tile, BK=64, 8 warps (4Mx2N), warp tile 32x32.
#define PAD2 72                     // halfs per smem row (144 B)
#define A_BUF_B (128 * PAD2 * 2)    // 18432
#define B_BUF_B (64 * PAD2 * 2)     // 9216
#define OFF_A   0
#define OFF_B   (2 * A_BUF_B)
#define SMEM_TOT (2 * A_BUF_B + 2 * B_BUF_B)   // 55296

template <bool CONCAT>
__global__ __launch_bounds__(256, 2) void gemm_mma(
    const float* __restrict__ A0, const float* __restrict__ A1,
    const __half* __restrict__ Bw,
    const float* __restrict__ bias, float* __restrict__ Cf, int N, int K)
{
    extern __shared__ char smem[];
    uint32_t sb = smem_u32(smem);

    int t = threadIdx.x;
    int wid = t >> 5, lane = t & 31;
    int wy = wid & 3, wx = wid >> 2;
    int row0 = blockIdx.y * 128;
    int col0 = blockIdx.x * 64;

    // A staging: thread -> (row 0..127, 32-float k-half)
    int ar = t >> 1;
    int ak = (t & 1) * 32;
    // B staging: thread -> (row 0..63, chunks {c, c+4} of 8 halfs)
    int br   = t >> 2;
    int bc16 = t & 3;

    float acc[2][4][4] = {};
    float4 pA[8];

    const int gnB = col0 + br;
    const bool bok = (gnB < N);

    auto loadgA = [&](int ch) {
        int k0 = ch * 64;
        const float* Aa; int ka;
        if (CONCAT && k0 >= 512) { Aa = A1; ka = k0 - 512; }
        else                     { Aa = A0; ka = k0; }
        const float* ap = Aa + (size_t)(row0 + ar) * 512 + ka + ak;
        #pragma unroll
        for (int j = 0; j < 8; j++)
            pA[j] = *(const float4*)(ap + j * 4);
    };
    auto cpasyncB = [&](int ch, int buf) {
        if (!bok) return;
        int k0 = ch * 64;
        const __half* sp = Bw + (size_t)gnB * K + k0;
        uint32_t base = sb + OFF_B + buf * B_BUF_B + (uint32_t)(br * PAD2) * 2;
        cpasync16(base + bc16 * 16,       sp + bc16 * 8);
        cpasync16(base + (bc16 + 4) * 16, sp + (bc16 + 4) * 8);
    };
    auto stageA = [&](int buf) {
        uint32_t base = (uint32_t)OFF_A + buf * A_BUF_B
                        + (uint32_t)(ar * PAD2 + ak) * 2;
        #pragma unroll
        for (int j = 0; j < 4; j++) {
            uint4 hp = cvt8h(pA[2 * j], pA[2 * j + 1]);
            *(uint4*)(smem + base + j * 16) = hp;
        }
    };

    int a_row_off = (lane & 7) + ((lane & 8) ? 8 : 0);
    int a_ch_off  = (lane & 16) ? 1 : 0;
    int b_row_off = (lane & 7) + ((lane & 16) ? 8 : 0);
    int b_ch_off  = (lane & 8) ? 1 : 0;

    int nch = K / 64;

    loadgA(0);
    cpasyncB(0, 0);
    asm volatile("cp.async.commit_group;" ::: "memory");
    stageA(0);
    asm volatile("cp.async.wait_group 0;" ::: "memory");
    __syncthreads();

    int buf = 0;
    for (int ch = 0; ch < nch; ch++) {
        int nxt = ch + 1;
        if (nxt < nch) {
            loadgA(nxt);
            cpasyncB(nxt, buf ^ 1);
            asm volatile("cp.async.commit_group;" ::: "memory");
        }

        uint32_t aB = sb + OFF_A + buf * A_BUF_B;
        uint32_t bB = sb + OFF_B + buf * B_BUF_B;
        #pragma unroll
        for (int ks = 0; ks < 4; ks++) {
            uint32_t ah[2][4], bh[2][4];
            int ac = (ks * 2 + a_ch_off) * 8;
            int bc = (ks * 2 + b_ch_off) * 8;
            #pragma unroll
            for (int mt = 0; mt < 2; mt++) {
                int r = wy * 32 + mt * 16 + a_row_off;
                ldm_x4(ah[mt], aB + (uint32_t)(r * PAD2 + ac) * 2);
            }
            #pragma unroll
            for (int nt2 = 0; nt2 < 2; nt2++) {
                int r = wx * 32 + nt2 * 16 + b_row_off;
                ldm_x4(bh[nt2], bB + (uint32_t)(r * PAD2 + bc) * 2);
            }
            #pragma unroll
            for (int mt = 0; mt < 2; mt++)
                #pragma unroll
                for (int nt = 0; nt < 4; nt++) {
                    uint32_t b0 = bh[nt >> 1][(nt & 1) * 2];
                    uint32_t b1 = bh[nt >> 1][(nt & 1) * 2 + 1];
                    mma16816h(acc[mt][nt], ah[mt], b0, b1);
                }
        }

        if (nxt < nch) stageA(buf ^ 1);
        asm volatile("cp.async.wait_group 0;" ::: "memory");
        __syncthreads();
        buf ^= 1;
    }

    // ---- epilogue ----
    int qr = lane >> 2;
    int qc = (lane & 3) * 2;
    #pragma unroll
    for (int mt = 0; mt < 2; mt++) {
        #pragma unroll
        for (int nt = 0; nt < 4; nt++) {
            int gm = row0 + wy * 32 + mt * 16 + qr;
            int gc = col0 + wx * 32 + nt * 8 + qc;
            float* c = acc[mt][nt];
            if (gc < N) {
                float b0 = bias[gc], b1 = bias[gc + 1];
                *(float2*)(Cf + (size_t)gm * N + gc)       = make_float2(c[0] + b0, c[1] + b1);
                *(float2*)(Cf + (size_t)(gm + 8) * N + gc) = make_float2(c[2] + b0, c[3] + b1);
            }
        }
    }
}

// ---------------- LayerNorm over last dim (512), in place -------------------
__global__ __launch_bounds__(128) void ln_kernel(
    float* __restrict__ h, const float* __restrict__ g, const float* __restrict__ b)
{
    int row = blockIdx.x;
    float4* hp = (float4*)(h + (size_t)row * LATENT);
    int t = threadIdx.x;
    float4 v = hp[t];
    float s  = v.x + v.y + v.z + v.w;
    float sq = v.x*v.x + v.y*v.y + v.z*v.z + v.w*v.w;
    #pragma unroll
    for (int o = 16; o; o >>= 1) {
        s  += __shfl_xor_sync(0xffffffffu, s, o);
        sq += __shfl_xor_sync(0xffffffffu, sq, o);
    }
    __shared__ float rs[4], rq[4];
    int lane = t & 31, wid = t >> 5;
    if (lane == 0) { rs[wid] = s; rq[wid] = sq; }
    __syncthreads();
    float S  = rs[0]+rs[1]+rs[2]+rs[3];
    float SQ = rq[0]+rq[1]+rq[2]+rq[3];
    float mu  = S * (1.0f / LATENT);
    float var = SQ * (1.0f / LATENT) - mu * mu;
    float r = rsqrtf(var + 1e-5f);
    float4 gv = ((const float4*)g)[t];
    float4 bv = ((const float4*)b)[t];
    v.x = (v.x - mu) * r * gv.x + bv.x;
    v.y = (v.y - mu) * r * gv.y + bv.y;
    v.z = (v.z - mu) * r * gv.z + bv.z;
    v.w = (v.w - mu) * r * gv.w + bv.w;
    hp[t] = v;
}

// ---------------- Oja update: one block per (b,h) ----------------------------
// W kept in registers for writeback; smem copy only for the matvec.
__global__ __launch_bounds__(128) void oja_kernel(
    const float* __restrict__ kvb, const float* __restrict__ W, float* __restrict__ out)
{
    int bh = blockIdx.x;
    const float* w = W   + (size_t)bh * (D * D);
    float*       o = out + (size_t)bh * (D * D);
    const float* kv = kvb + (size_t)(bh >> 3) * KVB_N + (size_t)(bh & 7) * (2 * D + 1);

    __shared__ float Ws[D * D];
    __shared__ float vs[D], ksc[D];
    __shared__ float wmax[4], wsum[4];
    int t = threadIdx.x;
    int wid = t >> 5, lane = t & 31;

    float4 wreg[8];
    #pragma unroll
    for (int j = 0; j < 8; j++) {
        int i = t + j * 128;
        float4 v = ((const float4*)w)[i];
        wreg[j] = v;
        ((float4*)Ws)[i] = v;
    }
    if (t < D) vs[t] = tanhf(kv[D + t]);
    __syncthreads();

    float logit = -1e30f;
    if (t < D) {
        float acc = 0.f;
        #pragma unroll 16
        for (int d = 0; d < D; d++)
            acc = fmaf(Ws[d * D + t], vs[d], acc);
        logit = kv[t] - acc;
    }
    float m = logit;
    #pragma unroll
    for (int s2 = 16; s2; s2 >>= 1) m = fmaxf(m, __shfl_xor_sync(0xffffffffu, m, s2));
    if (lane == 0) wmax[wid] = m;
    __syncthreads();
    float mm = fmaxf(wmax[0], wmax[1]);

    float e = 0.f, s = 0.f;
    if (t < D) { e = expf(logit - mm); s = e; }
    #pragma unroll
    for (int s2 = 16; s2; s2 >>= 1) s += __shfl_xor_sync(0xffffffffu, s, s2);
    if (lane == 0) wsum[wid] = s;
    __syncthreads();
    float ss = wsum[0] + wsum[1];

    if (t < D) {
        float lr = 1.0f / (1.0f + expf(-kv[2 * D]));
        ksc[t] = e * (lr / ss);
    }
    __syncthreads();

    #pragma unroll
    for (int j = 0; j < 8; j++) {
        int i = t + j * 128;
        float4 wv = wreg[j];
        int d  = i >> 4;
        int e0 = (i * 4) & (D - 1);
        float vd = vs[d];
        float4 r;
        r.x = fmaf(vd, ksc[e0 + 0], wv.x);
        r.y = fmaf(vd, ksc[e0 + 1], wv.y);
        r.z = fmaf(vd, ksc[e0 + 2], wv.z);
        r.w = fmaf(vd, ksc[e0 + 3], wv.w);
        ((float4*)o)[i] = r;
    }
}

// ---------------- launch -----------------------------------------------------
extern "C" void kernel_launch(void* const* d_in, const int* in_sizes, int n_in,
                              void* d_out, int out_size)
{
    const float* x     = (const float*)d_in[0];
    const float* z     = (const float*)d_in[1];
    const float* W     = (const float*)d_in[2];
    const float* ip_w  = (const float*)d_in[3];
    const float* ip_b  = (const float*)d_in[4];
    const float* ln_g  = (const float*)d_in[5];
    const float* ln_b  = (const float*)d_in[6];
    const float* mg_w  = (const float*)d_in[7];
    const float* mg_b  = (const float*)d_in[8];
    const float* kvb_w = (const float*)d_in[9];
    const float* kvb_b = (const float*)d_in[10];
    float* out = (float*)d_out;

    float *hP, *h2P, *kvbP;
    __half *ipw16, *mgw16, *kvbw16;
    cudaGetSymbolAddress((void**)&hP,     g_h);
    cudaGetSymbolAddress((void**)&h2P,    g_h2);
    cudaGetSymbolAddress((void**)&kvbP,   g_kvb);
    cudaGetSymbolAddress((void**)&ipw16,  g_ipwT);
    cudaGetSymbolAddress((void**)&mgw16,  g_mgwT);
    cudaGetSymbolAddress((void**)&kvbw16, g_kvbwT);

    cudaFuncSetAttribute(gemm_mma<false>,
                         cudaFuncAttributeMaxDynamicSharedMemorySize, SMEM_TOT);
    cudaFuncSetAttribute(gemm_mma<true>,
                         cudaFuncAttributeMaxDynamicSharedMemorySize, SMEM_TOT);

    // weight transpose + fp16 convert (64x64 tiles)
    tcvt_tiled<<<dim3(512/64, 512/64),  256>>>(ip_w,  ipw16,  512, 512);
    tcvt_tiled<<<dim3(1024/64, 512/64), 256>>>(mg_w,  mgw16,  1024, 512);
    tcvt_tiled<<<dim3(512/64, (KVB_N+63)/64), 256>>>(kvb_w, kvbw16, 512, KVB_N);

    // GEMM1: h = x @ ip_w + ip_b   (N=512, K=512)
    gemm_mma<false><<<dim3(8, 32), 256, SMEM_TOT>>>(
        x, nullptr, ipw16, ip_b, hP, 512, 512);

    // LayerNorm in place
    ln_kernel<<<B, 128>>>(hP, ln_g, ln_b);

    // GEMM2: h2 = [h, z] @ mg_w + mg_b  (N=512, K=1024)
    gemm_mma<true><<<dim3(8, 32), 256, SMEM_TOT>>>(
        hP, z, mgw16, mg_b, h2P, 512, 1024);

    // GEMM3: kvb = h2 @ kvb_w + kvb_b  (N=1032, K=512)
    gemm_mma<false><<<dim3((KVB_N + 63) / 64, 32), 256, SMEM_TOT>>>(
        h2P, nullptr, kvbw16, kvb_b, kvbP, KVB_N, 512);

    // Oja update
    oja_kernel<<<B * H, 128>>>(kvbP, W, out);
}

// round 14
// speedup vs baseline: 1.7161x; 1.7161x over previous
#include <cuda_runtime.h>
#include <cuda_fp16.h>
#include <math.h>
#include <stdint.h>

#define B 4096
#define LATENT 512
#define H 8
#define D 64
#define KVB_N (H * (2 * D + 1))   // 1032

// ---------------- scratch (device globals; no allocation allowed) -----------
__device__ float g_h[B * LATENT];                 // post-GEMM1 / post-LN (fp32)
__device__ float g_h2[B * LATENT];                // post-GEMM2 (fp32)
__device__ float g_kvb[B * KVB_N];                // post-GEMM3 (fp32)
__device__ __half g_ipwT[512 * 512];              // [N=512,K=512]  fp16
__device__ __half g_mgwT[512 * 1024];             // [N=512,K=1024] fp16
__device__ __half g_kvbwT[KVB_N * 512];           // [N=1032,K=512] fp16

// ---------------- helpers ----------------------------------------------------
__device__ __forceinline__ uint32_t smem_u32(const void* p) {
    uint32_t a;
    asm("{ .reg .u64 t; cvta.to.shared.u64 t, %1; cvt.u32.u64 %0, t; }"
        : "=r"(a) : "l"(p));
    return a;
}
__device__ __forceinline__ void ldm_x4(uint32_t (&r)[4], uint32_t addr) {
    asm volatile("ldmatrix.sync.aligned.m8n8.x4.shared.b16 {%0,%1,%2,%3}, [%4];"
        : "=r"(r[0]), "=r"(r[1]), "=r"(r[2]), "=r"(r[3]) : "r"(addr));
}
// non-volatile: pure register op, lets ptxas schedule/pipeline HMMAs.
__device__ __forceinline__ void mma16816h(float* c, const uint32_t* a,
                                          uint32_t b0, uint32_t b1) {
    asm("mma.sync.aligned.m16n8k16.row.col.f32.f16.f16.f32 "
        "{%0,%1,%2,%3}, {%4,%5,%6,%7}, {%8,%9}, {%0,%1,%2,%3};"
        : "+f"(c[0]), "+f"(c[1]), "+f"(c[2]), "+f"(c[3])
        : "r"(a[0]), "r"(a[1]), "r"(a[2]), "r"(a[3]), "r"(b0), "r"(b1));
}
__device__ __forceinline__ void cpasync16(uint32_t dst, const void* src) {
    asm volatile("cp.async.ca.shared.global [%0], [%1], 16;"
                 :: "r"(dst), "l"(src) : "memory");
}
// convert 8 fp32 -> 8 fp16, packed uint4
__device__ __forceinline__ uint4 cvt8h(const float4& a, const float4& b) {
    __half2 p0 = __floats2half2_rn(a.x, a.y);
    __half2 p1 = __floats2half2_rn(a.z, a.w);
    __half2 p2 = __floats2half2_rn(b.x, b.y);
    __half2 p3 = __floats2half2_rn(b.z, b.w);
    uint4 r;
    r.x = *(uint32_t*)&p0; r.y = *(uint32_t*)&p1;
    r.z = *(uint32_t*)&p2; r.w = *(uint32_t*)&p3;
    return r;
}

// ---------------- weight transpose+convert (64x64 tiles) --------------------
// src [K,N] fp32 -> dst [N,K] fp16
__global__ __launch_bounds__(256) void tcvt_tiled(
    const float* __restrict__ src, __half* __restrict__ dst, int K, int N)
{
    __shared__ __half th[64][72];
    int k0 = blockIdx.x * 64, n0 = blockIdx.y * 64;
    int t = threadIdx.x;
    {
        int r  = t >> 2;             // 0..63 (k within tile)
        int c0 = (t & 3) * 16;       // n within tile
        const float* sp = src + (size_t)(k0 + r) * N + n0 + c0;
        #pragma unroll
        for (int j = 0; j < 4; j++) {
            int gn = n0 + c0 + j * 4;
            float4 v = make_float4(0.f, 0.f, 0.f, 0.f);
            if (gn + 3 < N) {
                v = *(const float4*)(sp + j * 4);
            } else {
                if (gn + 0 < N) v.x = sp[j * 4 + 0];
                if (gn + 1 < N) v.y = sp[j * 4 + 1];
                if (gn + 2 < N) v.z = sp[j * 4 + 2];
                if (gn + 3 < N) v.w = sp[j * 4 + 3];
            }
            int c = c0 + j * 4;
            th[r][c + 0] = __float2half_rn(v.x);
            th[r][c + 1] = __float2half_rn(v.y);
            th[r][c + 2] = __float2half_rn(v.z);
            th[r][c + 3] = __float2half_rn(v.w);
        }
    }
    __syncthreads();
    {
        int n  = t >> 2;             // n within tile
        int kc = (t & 3) * 16;       // k within tile
        int gn = n0 + n;
        if (gn < N) {
            __half hb[16];
            #pragma unroll
            for (int j = 0; j < 16; j++) hb[j] = th[kc + j][n];
            uint4* hd = (uint4*)(dst + (size_t)gn * K + k0 + kc);
            hd[0] = *(uint4*)&hb[0];
            hd[1] = *(uint4*)&hb[8];
        }
    }
}

// ---------------- pipelined mma.sync GEMM (plain fp16, BK=32) ----------------
// C = A @ Bw^T + bias; A fp32 -> fp16 on stage; Bw fp16.
// 128x64 block tile, BK=32, 8 warps (4Mx2N), warp tile 32x32.  [R11 geometry]
#define PAD 40
#define A_BUF_B (128 * PAD * 2)     // 10240
#define B_BUF_B (64 * PAD * 2)      // 5120
#define OFF_A   0
#define OFF_B   (2 * A_BUF_B)
#define SMEM_TOT (2 * A_BUF_B + 2 * B_BUF_B)   // 30720

template <bool CONCAT>
__global__ __launch_bounds__(256, 2) void gemm_mma(
    const float* __restrict__ A0, const float* __restrict__ A1,
    const __half* __restrict__ Bw,
    const float* __restrict__ bias, float* __restrict__ Cf, int N, int K)
{
    extern __shared__ char smem[];
    uint32_t sb = smem_u32(smem);

    int t = threadIdx.x;
    int wid = t >> 5, lane = t & 31;
    int wy = wid & 3, wx = wid >> 2;
    int row0 = blockIdx.y * 128;
    int col0 = blockIdx.x * 64;

    int srow = t >> 2;
    int sc16 = t & 3;

    float acc[2][4][4] = {};
    float4 pA[2][2];

    const int gnB = col0 + srow;
    const bool bok = (gnB < N);

    auto loadgA = [&](int ch) {
        int k0 = ch * 32;
        const float* Aa; int ka;
        if (CONCAT && k0 >= 512) { Aa = A1; ka = k0 - 512; }
        else                     { Aa = A0; ka = k0; }
        #pragma unroll
        for (int i = 0; i < 2; i++) {
            int r = srow + i * 64;
            const float* ap = Aa + (size_t)(row0 + r) * 512 + ka + sc16 * 8;
            pA[i][0] = *(const float4*)ap;
            pA[i][1] = *(const float4*)(ap + 4);
        }
    };
    auto cpasyncB = [&](int ch, int buf) {
        if (!bok) return;
        int k0 = ch * 32;
        uint32_t d = sb + OFF_B + buf * B_BUF_B
                     + (uint32_t)(srow * PAD + sc16 * 8) * 2;
        cpasync16(d, Bw + (size_t)gnB * K + k0 + sc16 * 8);
    };
    auto stageA = [&](int buf) {
        #pragma unroll
        for (int i = 0; i < 2; i++) {
            int r = srow + i * 64;
            uint4 hp = cvt8h(pA[i][0], pA[i][1]);
            *(uint4*)(smem + OFF_A + buf * A_BUF_B
                      + (uint32_t)(r * PAD + sc16 * 8) * 2) = hp;
        }
    };

    int a_row_off = (lane & 7) + ((lane & 8) ? 8 : 0);
    int a_ch_off  = (lane & 16) ? 1 : 0;
    int b_row_off = (lane & 7) + ((lane & 16) ? 8 : 0);
    int b_ch_off  = (lane & 8) ? 1 : 0;

    int nch = K / 32;

    loadgA(0);
    cpasyncB(0, 0);
    asm volatile("cp.async.commit_group;" ::: "memory");
    stageA(0);
    asm volatile("cp.async.wait_group 0;" ::: "memory");
    __syncthreads();

    int buf = 0;
    for (int ch = 0; ch < nch; ch++) {
        int nxt = ch + 1;
        if (nxt < nch) {
            loadgA(nxt);
            cpasyncB(nxt, buf ^ 1);
            asm volatile("cp.async.commit_group;" ::: "memory");
        }

        uint32_t aB = sb + OFF_A + buf * A_BUF_B;
        uint32_t bB = sb + OFF_B + buf * B_BUF_B;
        #pragma unroll
        for (int ks = 0; ks < 2; ks++) {
            uint32_t ah[2][4], bh[2][4];
            int ac = (ks * 2 + a_ch_off) * 8;
            int bc = (ks * 2 + b_ch_off) * 8;
            #pragma unroll
            for (int mt = 0; mt < 2; mt++) {
                int r = wy * 32 + mt * 16 + a_row_off;
                ldm_x4(ah[mt], aB + (uint32_t)(r * PAD + ac) * 2);
            }
            #pragma unroll
            for (int nt2 = 0; nt2 < 2; nt2++) {
                int r = wx * 32 + nt2 * 16 + b_row_off;
                ldm_x4(bh[nt2], bB + (uint32_t)(r * PAD + bc) * 2);
            }
            #pragma unroll
            for (int mt = 0; mt < 2; mt++)
                #pragma unroll
                for (int nt = 0; nt < 4; nt++) {
                    uint32_t b0 = bh[nt >> 1][(nt & 1) * 2];
                    uint32_t b1 = bh[nt >> 1][(nt & 1) * 2 + 1];
                    mma16816h(acc[mt][nt], ah[mt], b0, b1);
                }
        }

        if (nxt < nch) stageA(buf ^ 1);
        asm volatile("cp.async.wait_group 0;" ::: "memory");
        __syncthreads();
        buf ^= 1;
    }

    // ---- epilogue ----
    int qr = lane >> 2;
    int qc = (lane & 3) * 2;
    #pragma unroll
    for (int mt = 0; mt < 2; mt++) {
        #pragma unroll
        for (int nt = 0; nt < 4; nt++) {
            int gm = row0 + wy * 32 + mt * 16 + qr;
            int gc = col0 + wx * 32 + nt * 8 + qc;
            float* c = acc[mt][nt];
            if (gc < N) {
                float b0 = bias[gc], b1 = bias[gc + 1];
                *(float2*)(Cf + (size_t)gm * N + gc)       = make_float2(c[0] + b0, c[1] + b1);
                *(float2*)(Cf + (size_t)(gm + 8) * N + gc) = make_float2(c[2] + b0, c[3] + b1);
            }
        }
    }
}

// ---------------- LayerNorm over last dim (512), in place -------------------
__global__ __launch_bounds__(128) void ln_kernel(
    float* __restrict__ h, const float* __restrict__ g, const float* __restrict__ b)
{
    int row = blockIdx.x;
    float4* hp = (float4*)(h + (size_t)row * LATENT);
    int t = threadIdx.x;
    float4 v = hp[t];
    float s  = v.x + v.y + v.z + v.w;
    float sq = v.x*v.x + v.y*v.y + v.z*v.z + v.w*v.w;
    #pragma unroll
    for (int o = 16; o; o >>= 1) {
        s  += __shfl_xor_sync(0xffffffffu, s, o);
        sq += __shfl_xor_sync(0xffffffffu, sq, o);
    }
    __shared__ float rs[4], rq[4];
    int lane = t & 31, wid = t >> 5;
    if (lane == 0) { rs[wid] = s; rq[wid] = sq; }
    __syncthreads();
    float S  = rs[0]+rs[1]+rs[2]+rs[3];
    float SQ = rq[0]+rq[1]+rq[2]+rq[3];
    float mu  = S * (1.0f / LATENT);
    float var = SQ * (1.0f / LATENT) - mu * mu;
    float r = rsqrtf(var + 1e-5f);
    float4 gv = ((const float4*)g)[t];
    float4 bv = ((const float4*)b)[t];
    v.x = (v.x - mu) * r * gv.x + bv.x;
    v.y = (v.y - mu) * r * gv.y + bv.y;
    v.z = (v.z - mu) * r * gv.z + bv.z;
    v.w = (v.w - mu) * r * gv.w + bv.w;
    hp[t] = v;
}

// ---------------- Oja update: one block per (b,h) ----------------------------
// W kept in registers for writeback; smem copy only for the matvec.
__global__ __launch_bounds__(128) void oja_kernel(
    const float* __restrict__ kvb, const float* __restrict__ W, float* __restrict__ out)
{
    int bh = blockIdx.x;
    const float* w = W   + (size_t)bh * (D * D);
    float*       o = out + (size_t)bh * (D * D);
    const float* kv = kvb + (size_t)(bh >> 3) * KVB_N + (size_t)(bh & 7) * (2 * D + 1);

    __shared__ float Ws[D * D];
    __shared__ float vs[D], ksc[D];
    __shared__ float wmax[4], wsum[4];
    int t = threadIdx.x;
    int wid = t >> 5, lane = t & 31;

    float4 wreg[8];
    #pragma unroll
    for (int j = 0; j < 8; j++) {
        int i = t + j * 128;
        float4 v = ((const float4*)w)[i];
        wreg[j] = v;
        ((float4*)Ws)[i] = v;
    }
    if (t < D) vs[t] = tanhf(kv[D + t]);
    __syncthreads();

    float logit = -1e30f;
    if (t < D) {
        float acc = 0.f;
        #pragma unroll 16
        for (int d = 0; d < D; d++)
            acc = fmaf(Ws[d * D + t], vs[d], acc);
        logit = kv[t] - acc;
    }
    float m = logit;
    #pragma unroll
    for (int s2 = 16; s2; s2 >>= 1) m = fmaxf(m, __shfl_xor_sync(0xffffffffu, m, s2));
    if (lane == 0) wmax[wid] = m;
    __syncthreads();
    float mm = fmaxf(wmax[0], wmax[1]);

    float e = 0.f, s = 0.f;
    if (t < D) { e = expf(logit - mm); s = e; }
    #pragma unroll
    for (int s2 = 16; s2; s2 >>= 1) s += __shfl_xor_sync(0xffffffffu, s, s2);
    if (lane == 0) wsum[wid] = s;
    __syncthreads();
    float ss = wsum[0] + wsum[1];

    if (t < D) {
        float lr = 1.0f / (1.0f + expf(-kv[2 * D]));
        ksc[t] = e * (lr / ss);
    }
    __syncthreads();

    #pragma unroll
    for (int j = 0; j < 8; j++) {
        int i = t + j * 128;
        float4 wv = wreg[j];
        int d  = i >> 4;
        int e0 = (i * 4) & (D - 1);
        float vd = vs[d];
        float4 r;
        r.x = fmaf(vd, ksc[e0 + 0], wv.x);
        r.y = fmaf(vd, ksc[e0 + 1], wv.y);
        r.z = fmaf(vd, ksc[e0 + 2], wv.z);
        r.w = fmaf(vd, ksc[e0 + 3], wv.w);
        ((float4*)o)[i] = r;
    }
}

// ---------------- launch -----------------------------------------------------
extern "C" void kernel_launch(void* const* d_in, const int* in_sizes, int n_in,
                              void* d_out, int out_size)
{
    const float* x     = (const float*)d_in[0];
    const float* z     = (const float*)d_in[1];
    const float* W     = (const float*)d_in[2];
    const float* ip_w  = (const float*)d_in[3];
    const float* ip_b  = (const float*)d_in[4];
    const float* ln_g  = (const float*)d_in[5];
    const float* ln_b  = (const float*)d_in[6];
    const float* mg_w  = (const float*)d_in[7];
    const float* mg_b  = (const float*)d_in[8];
    const float* kvb_w = (const float*)d_in[9];
    const float* kvb_b = (const float*)d_in[10];
    float* out = (float*)d_out;

    float *hP, *h2P, *kvbP;
    __half *ipw16, *mgw16, *kvbw16;
    cudaGetSymbolAddress((void**)&hP,     g_h);
    cudaGetSymbolAddress((void**)&h2P,    g_h2);
    cudaGetSymbolAddress((void**)&kvbP,   g_kvb);
    cudaGetSymbolAddress((void**)&ipw16,  g_ipwT);
    cudaGetSymbolAddress((void**)&mgw16,  g_mgwT);
    cudaGetSymbolAddress((void**)&kvbw16, g_kvbwT);

    cudaFuncSetAttribute(gemm_mma<false>,
                         cudaFuncAttributeMaxDynamicSharedMemorySize, SMEM_TOT);
    cudaFuncSetAttribute(gemm_mma<true>,
                         cudaFuncAttributeMaxDynamicSharedMemorySize, SMEM_TOT);

    // weight transpose + fp16 convert (64x64 tiles)
    tcvt_tiled<<<dim3(512/64, 512/64),  256>>>(ip_w,  ipw16,  512, 512);
    tcvt_tiled<<<dim3(1024/64, 512/64), 256>>>(mg_w,  mgw16,  1024, 512);
    tcvt_tiled<<<dim3(512/64, (KVB_N+63)/64), 256>>>(kvb_w, kvbw16, 512, KVB_N);

    // GEMM1: h = x @ ip_w + ip_b   (N=512, K=512)
    gemm_mma<false><<<dim3(8, 32), 256, SMEM_TOT>>>(
        x, nullptr, ipw16, ip_b, hP, 512, 512);

    // LayerNorm in place
    ln_kernel<<<B, 128>>>(hP, ln_g, ln_b);

    // GEMM2: h2 = [h, z] @ mg_w + mg_b  (N=512, K=1024)
    gemm_mma<true><<<dim3(8, 32), 256, SMEM_TOT>>>(
        hP, z, mgw16, mg_b, h2P, 512, 1024);

    // GEMM3: kvb = h2 @ kvb_w + kvb_b  (N=1032, K=512)
    gemm_mma<false><<<dim3((KVB_N + 63) / 64, 32), 256, SMEM_TOT>>>(
        h2P, nullptr, kvbw16, kvb_b, kvbP, KVB_N, 512);

    // Oja update
    oja_kernel<<<B * H, 128>>>(kvbP, W, out);
}

// round 15
// speedup vs baseline: 1.7592x; 1.0251x over previous
#include <cuda_runtime.h>
#include <cuda_fp16.h>
#include <math.h>
#include <stdint.h>

#define B 4096
#define LATENT 512
#define H 8
#define D 64
#define KVB_N (H * (2 * D + 1))   // 1032

// ---------------- scratch (device globals; no allocation allowed) -----------
__device__ float  g_h[B * LATENT];                // post-GEMM1 (fp32, for LN)
__device__ float  g_kvb[B * KVB_N];               // post-GEMM3 (fp32)
__device__ __half g_x16[B * 512];                 // x  as fp16
__device__ __half g_z16[B * 512];                 // z  as fp16
__device__ __half g_h16[B * 512];                 // LN(h) as fp16
__device__ __half g_h216[B * 512];                // h2 as fp16
__device__ __half g_ipwT[512 * 512];              // [N=512,K=512]  fp16
__device__ __half g_mgwT[512 * 1024];             // [N=512,K=1024] fp16
__device__ __half g_kvbwT[KVB_N * 512];           // [N=1032,K=512] fp16

// ---------------- helpers ----------------------------------------------------
__device__ __forceinline__ uint32_t smem_u32(const void* p) {
    uint32_t a;
    asm("{ .reg .u64 t; cvta.to.shared.u64 t, %1; cvt.u32.u64 %0, t; }"
        : "=r"(a) : "l"(p));
    return a;
}
__device__ __forceinline__ void ldm_x4(uint32_t (&r)[4], uint32_t addr) {
    asm volatile("ldmatrix.sync.aligned.m8n8.x4.shared.b16 {%0,%1,%2,%3}, [%4];"
        : "=r"(r[0]), "=r"(r[1]), "=r"(r[2]), "=r"(r[3]) : "r"(addr));
}
// non-volatile: pure register op, lets ptxas schedule/pipeline HMMAs.
__device__ __forceinline__ void mma16816h(float* c, const uint32_t* a,
                                          uint32_t b0, uint32_t b1) {
    asm("mma.sync.aligned.m16n8k16.row.col.f32.f16.f16.f32 "
        "{%0,%1,%2,%3}, {%4,%5,%6,%7}, {%8,%9}, {%0,%1,%2,%3};"
        : "+f"(c[0]), "+f"(c[1]), "+f"(c[2]), "+f"(c[3])
        : "r"(a[0]), "r"(a[1]), "r"(a[2]), "r"(a[3]), "r"(b0), "r"(b1));
}
__device__ __forceinline__ void cpasync16(uint32_t dst, const void* src) {
    asm volatile("cp.async.ca.shared.global [%0], [%1], 16;"
                 :: "r"(dst), "l"(src) : "memory");
}

// ---------------- elementwise fp32 -> fp16 -----------------------------------
__global__ __launch_bounds__(256) void cvt16_kernel(
    const float* __restrict__ src, __half* __restrict__ dst, int n4)
{
    int i = blockIdx.x * 256 + threadIdx.x;
    if (i >= n4) return;
    float4 v = ((const float4*)src)[i];
    __half2 p0 = __floats2half2_rn(v.x, v.y);
    __half2 p1 = __floats2half2_rn(v.z, v.w);
    uint2 r; r.x = *(uint32_t*)&p0; r.y = *(uint32_t*)&p1;
    ((uint2*)dst)[i] = r;
}

// ---------------- weight transpose+convert (64x64 tiles) --------------------
// src [K,N] fp32 -> dst [N,K] fp16
__global__ __launch_bounds__(256) void tcvt_tiled(
    const float* __restrict__ src, __half* __restrict__ dst, int K, int N)
{
    __shared__ __half th[64][72];
    int k0 = blockIdx.x * 64, n0 = blockIdx.y * 64;
    int t = threadIdx.x;
    {
        int r  = t >> 2;
        int c0 = (t & 3) * 16;
        const float* sp = src + (size_t)(k0 + r) * N + n0 + c0;
        #pragma unroll
        for (int j = 0; j < 4; j++) {
            int gn = n0 + c0 + j * 4;
            float4 v = make_float4(0.f, 0.f, 0.f, 0.f);
            if (gn + 3 < N) {
                v = *(const float4*)(sp + j * 4);
            } else {
                if (gn + 0 < N) v.x = sp[j * 4 + 0];
                if (gn + 1 < N) v.y = sp[j * 4 + 1];
                if (gn + 2 < N) v.z = sp[j * 4 + 2];
                if (gn + 3 < N) v.w = sp[j * 4 + 3];
            }
            int c = c0 + j * 4;
            th[r][c + 0] = __float2half_rn(v.x);
            th[r][c + 1] = __float2half_rn(v.y);
            th[r][c + 2] = __float2half_rn(v.z);
            th[r][c + 3] = __float2half_rn(v.w);
        }
    }
    __syncthreads();
    {
        int n  = t >> 2;
        int kc = (t & 3) * 16;
        int gn = n0 + n;
        if (gn < N) {
            __half hb[16];
            #pragma unroll
            for (int j = 0; j < 16; j++) hb[j] = th[kc + j][n];
            uint4* hd = (uint4*)(dst + (size_t)gn * K + k0 + kc);
            hd[0] = *(uint4*)&hb[0];
            hd[1] = *(uint4*)&hb[8];
        }
    }
}

// ---------------- pipelined mma.sync GEMM (all-fp16, cp.async both sides) ----
// C = A @ Bw^T + bias; A fp16 [M,512] (two arrays when CONCAT), Bw fp16 [N,K].
// 128x64 block tile, BK=32, 8 warps (4Mx2N), warp tile 32x32, 3 blocks/SM.
#define PAD 40
#define A_BUF_B (128 * PAD * 2)     // 10240
#define B_BUF_B (64 * PAD * 2)      // 5120
#define OFF_A   0
#define OFF_B   (2 * A_BUF_B)
#define SMEM_TOT (2 * A_BUF_B + 2 * B_BUF_B)   // 30720

template <bool CONCAT, bool HALF_OUT>
__global__ __launch_bounds__(256, 3) void gemm_mma(
    const __half* __restrict__ A0, const __half* __restrict__ A1,
    const __half* __restrict__ Bw,
    const float* __restrict__ bias, float* __restrict__ Cf,
    __half* __restrict__ Ch, int N, int K)
{
    extern __shared__ char smem[];
    uint32_t sb = smem_u32(smem);

    int t = threadIdx.x;
    int wid = t >> 5, lane = t & 31;
    int wy = wid & 3, wx = wid >> 2;
    int row0 = blockIdx.y * 128;
    int col0 = blockIdx.x * 64;

    // B staging: thread -> (row 0..63, 16B k-chunk 0..3)
    int br   = t >> 2;
    int bc16 = t & 3;

    float acc[2][4][4] = {};

    const int gnB = col0 + br;
    const bool bok = (gnB < N);

    auto cpasyncAB = [&](int ch, int buf) {
        int k0 = ch * 32;
        const __half* Aa; int ka;
        if (CONCAT && k0 >= 512) { Aa = A1; ka = k0 - 512; }
        else                     { Aa = A0; ka = k0; }
        // A: 512 chunks of 16B, 2 per thread
        #pragma unroll
        for (int i = 0; i < 2; i++) {
            int id = t + i * 256;
            int r = id >> 2, c = id & 3;
            uint32_t d = sb + OFF_A + buf * A_BUF_B
                         + (uint32_t)(r * PAD + c * 8) * 2;
            cpasync16(d, Aa + (size_t)(row0 + r) * 512 + ka + c * 8);
        }
        // B: 256 chunks, 1 per thread
        if (bok) {
            uint32_t d = sb + OFF_B + buf * B_BUF_B
                         + (uint32_t)(br * PAD + bc16 * 8) * 2;
            cpasync16(d, Bw + (size_t)gnB * K + k0 + bc16 * 8);
        }
    };

    int a_row_off = (lane & 7) + ((lane & 8) ? 8 : 0);
    int a_ch_off  = (lane & 16) ? 1 : 0;
    int b_row_off = (lane & 7) + ((lane & 16) ? 8 : 0);
    int b_ch_off  = (lane & 8) ? 1 : 0;

    int nch = K / 32;

    cpasyncAB(0, 0);
    asm volatile("cp.async.commit_group;" ::: "memory");
    asm volatile("cp.async.wait_group 0;" ::: "memory");
    __syncthreads();

    int buf = 0;
    for (int ch = 0; ch < nch; ch++) {
        int nxt = ch + 1;
        if (nxt < nch) {
            cpasyncAB(nxt, buf ^ 1);
            asm volatile("cp.async.commit_group;" ::: "memory");
        }

        uint32_t aB = sb + OFF_A + buf * A_BUF_B;
        uint32_t bB = sb + OFF_B + buf * B_BUF_B;
        #pragma unroll
        for (int ks = 0; ks < 2; ks++) {
            uint32_t ah[2][4], bh[2][4];
            int ac = (ks * 2 + a_ch_off) * 8;
            int bc = (ks * 2 + b_ch_off) * 8;
            #pragma unroll
            for (int mt = 0; mt < 2; mt++) {
                int r = wy * 32 + mt * 16 + a_row_off;
                ldm_x4(ah[mt], aB + (uint32_t)(r * PAD + ac) * 2);
            }
            #pragma unroll
            for (int nt2 = 0; nt2 < 2; nt2++) {
                int r = wx * 32 + nt2 * 16 + b_row_off;
                ldm_x4(bh[nt2], bB + (uint32_t)(r * PAD + bc) * 2);
            }
            #pragma unroll
            for (int mt = 0; mt < 2; mt++)
                #pragma unroll
                for (int nt = 0; nt < 4; nt++) {
                    uint32_t b0 = bh[nt >> 1][(nt & 1) * 2];
                    uint32_t b1 = bh[nt >> 1][(nt & 1) * 2 + 1];
                    mma16816h(acc[mt][nt], ah[mt], b0, b1);
                }
        }

        asm volatile("cp.async.wait_group 0;" ::: "memory");
        __syncthreads();
        buf ^= 1;
    }

    // ---- epilogue ----
    int qr = lane >> 2;
    int qc = (lane & 3) * 2;
    #pragma unroll
    for (int mt = 0; mt < 2; mt++) {
        #pragma unroll
        for (int nt = 0; nt < 4; nt++) {
            int gm = row0 + wy * 32 + mt * 16 + qr;
            int gc = col0 + wx * 32 + nt * 8 + qc;
            float* c = acc[mt][nt];
            if (gc < N) {
                float b0 = bias[gc], b1 = bias[gc + 1];
                float v0 = c[0] + b0, v1 = c[1] + b1;
                float v2 = c[2] + b0, v3 = c[3] + b1;
                if (HALF_OUT) {
                    __half2 p0 = __floats2half2_rn(v0, v1);
                    __half2 p1 = __floats2half2_rn(v2, v3);
                    *(__half2*)(Ch + (size_t)gm * N + gc)       = p0;
                    *(__half2*)(Ch + (size_t)(gm + 8) * N + gc) = p1;
                } else {
                    *(float2*)(Cf + (size_t)gm * N + gc)       = make_float2(v0, v1);
                    *(float2*)(Cf + (size_t)(gm + 8) * N + gc) = make_float2(v2, v3);
                }
            }
        }
    }
}

// ---------------- LayerNorm: fp32 in, fp16 out -------------------------------
__global__ __launch_bounds__(128) void ln_kernel(
    const float* __restrict__ h, const float* __restrict__ g, const float* __restrict__ b,
    __half* __restrict__ o16)
{
    int row = blockIdx.x;
    const float4* hp = (const float4*)(h + (size_t)row * LATENT);
    int t = threadIdx.x;
    float4 v = hp[t];
    float s  = v.x + v.y + v.z + v.w;
    float sq = v.x*v.x + v.y*v.y + v.z*v.z + v.w*v.w;
    #pragma unroll
    for (int o = 16; o; o >>= 1) {
        s  += __shfl_xor_sync(0xffffffffu, s, o);
        sq += __shfl_xor_sync(0xffffffffu, sq, o);
    }
    __shared__ float rs[4], rq[4];
    int lane = t & 31, wid = t >> 5;
    if (lane == 0) { rs[wid] = s; rq[wid] = sq; }
    __syncthreads();
    float S  = rs[0]+rs[1]+rs[2]+rs[3];
    float SQ = rq[0]+rq[1]+rq[2]+rq[3];
    float mu  = S * (1.0f / LATENT);
    float var = SQ * (1.0f / LATENT) - mu * mu;
    float r = rsqrtf(var + 1e-5f);
    float4 gv = ((const float4*)g)[t];
    float4 bv = ((const float4*)b)[t];
    float o0 = (v.x - mu) * r * gv.x + bv.x;
    float o1 = (v.y - mu) * r * gv.y + bv.y;
    float o2 = (v.z - mu) * r * gv.z + bv.z;
    float o3 = (v.w - mu) * r * gv.w + bv.w;
    __half2 p0 = __floats2half2_rn(o0, o1);
    __half2 p1 = __floats2half2_rn(o2, o3);
    uint2 pk; pk.x = *(uint32_t*)&p0; pk.y = *(uint32_t*)&p1;
    ((uint2*)(o16 + (size_t)row * LATENT))[t] = pk;
}

// ---------------- Oja update: one block per (b,h) ----------------------------
// W kept in registers for writeback; smem copy only for the matvec.
__global__ __launch_bounds__(128) void oja_kernel(
    const float* __restrict__ kvb, const float* __restrict__ W, float* __restrict__ out)
{
    int bh = blockIdx.x;
    const float* w = W   + (size_t)bh * (D * D);
    float*       o = out + (size_t)bh * (D * D);
    const float* kv = kvb + (size_t)(bh >> 3) * KVB_N + (size_t)(bh & 7) * (2 * D + 1);

    __shared__ float Ws[D * D];
    __shared__ float vs[D], ksc[D];
    __shared__ float wmax[4], wsum[4];
    int t = threadIdx.x;
    int wid = t >> 5, lane = t & 31;

    float4 wreg[8];
    #pragma unroll
    for (int j = 0; j < 8; j++) {
        int i = t + j * 128;
        float4 v = ((const float4*)w)[i];
        wreg[j] = v;
        ((float4*)Ws)[i] = v;
    }
    if (t < D) vs[t] = tanhf(kv[D + t]);
    __syncthreads();

    float logit = -1e30f;
    if (t < D) {
        float acc = 0.f;
        #pragma unroll 16
        for (int d = 0; d < D; d++)
            acc = fmaf(Ws[d * D + t], vs[d], acc);
        logit = kv[t] - acc;
    }
    float m = logit;
    #pragma unroll
    for (int s2 = 16; s2; s2 >>= 1) m = fmaxf(m, __shfl_xor_sync(0xffffffffu, m, s2));
    if (lane == 0) wmax[wid] = m;
    __syncthreads();
    float mm = fmaxf(wmax[0], wmax[1]);

    float e = 0.f, s = 0.f;
    if (t < D) { e = expf(logit - mm); s = e; }
    #pragma unroll
    for (int s2 = 16; s2; s2 >>= 1) s += __shfl_xor_sync(0xffffffffu, s, s2);
    if (lane == 0) wsum[wid] = s;
    __syncthreads();
    float ss = wsum[0] + wsum[1];

    if (t < D) {
        float lr = 1.0f / (1.0f + expf(-kv[2 * D]));
        ksc[t] = e * (lr / ss);
    }
    __syncthreads();

    #pragma unroll
    for (int j = 0; j < 8; j++) {
        int i = t + j * 128;
        float4 wv = wreg[j];
        int d  = i >> 4;
        int e0 = (i * 4) & (D - 1);
        float vd = vs[d];
        float4 r;
        r.x = fmaf(vd, ksc[e0 + 0], wv.x);
        r.y = fmaf(vd, ksc[e0 + 1], wv.y);
        r.z = fmaf(vd, ksc[e0 + 2], wv.z);
        r.w = fmaf(vd, ksc[e0 + 3], wv.w);
        ((float4*)o)[i] = r;
    }
}

// ---------------- launch -----------------------------------------------------
extern "C" void kernel_launch(void* const* d_in, const int* in_sizes, int n_in,
                              void* d_out, int out_size)
{
    const float* x     = (const float*)d_in[0];
    const float* z     = (const float*)d_in[1];
    const float* W     = (const float*)d_in[2];
    const float* ip_w  = (const float*)d_in[3];
    const float* ip_b  = (const float*)d_in[4];
    const float* ln_g  = (const float*)d_in[5];
    const float* ln_b  = (const float*)d_in[6];
    const float* mg_w  = (const float*)d_in[7];
    const float* mg_b  = (const float*)d_in[8];
    const float* kvb_w = (const float*)d_in[9];
    const float* kvb_b = (const float*)d_in[10];
    float* out = (float*)d_out;

    float *hP, *kvbP;
    __half *x16, *z16, *h16, *h216, *ipw16, *mgw16, *kvbw16;
    cudaGetSymbolAddress((void**)&hP,     g_h);
    cudaGetSymbolAddress((void**)&kvbP,   g_kvb);
    cudaGetSymbolAddress((void**)&x16,    g_x16);
    cudaGetSymbolAddress((void**)&z16,    g_z16);
    cudaGetSymbolAddress((void**)&h16,    g_h16);
    cudaGetSymbolAddress((void**)&h216,   g_h216);
    cudaGetSymbolAddress((void**)&ipw16,  g_ipwT);
    cudaGetSymbolAddress((void**)&mgw16,  g_mgwT);
    cudaGetSymbolAddress((void**)&kvbw16, g_kvbwT);

    cudaFuncSetAttribute((const void*)gemm_mma<false,false>,
                         cudaFuncAttributeMaxDynamicSharedMemorySize, SMEM_TOT);
    cudaFuncSetAttribute((const void*)gemm_mma<true,true>,
                         cudaFuncAttributeMaxDynamicSharedMemorySize, SMEM_TOT);

    // prep: activations -> fp16; weights transpose+convert
    cvt16_kernel<<<(B*512/4 + 255)/256, 256>>>(x, x16, B*512/4);
    cvt16_kernel<<<(B*512/4 + 255)/256, 256>>>(z, z16, B*512/4);
    tcvt_tiled<<<dim3(512/64, 512/64),  256>>>(ip_w,  ipw16,  512, 512);
    tcvt_tiled<<<dim3(1024/64, 512/64), 256>>>(mg_w,  mgw16,  1024, 512);
    tcvt_tiled<<<dim3(512/64, (KVB_N+63)/64), 256>>>(kvb_w, kvbw16, 512, KVB_N);

    // GEMM1: h = x @ ip_w + ip_b   (N=512, K=512) -> fp32
    gemm_mma<false,false><<<dim3(8, 32), 256, SMEM_TOT>>>(
        x16, nullptr, ipw16, ip_b, hP, nullptr, 512, 512);

    // LN: fp32 in -> fp16 out
    ln_kernel<<<B, 128>>>(hP, ln_g, ln_b, h16);

    // GEMM2: h2 = [h, z] @ mg_w + mg_b  (N=512, K=1024) -> fp16
    gemm_mma<true,true><<<dim3(8, 32), 256, SMEM_TOT>>>(
        h16, z16, mgw16, mg_b, nullptr, h216, 512, 1024);

    // GEMM3: kvb = h2 @ kvb_w + kvb_b  (N=1032, K=512) -> fp32
    gemm_mma<false,false><<<dim3((KVB_N + 63) / 64, 32), 256, SMEM_TOT>>>(
        h216, nullptr, kvbw16, kvb_b, kvbP, nullptr, KVB_N, 512);

    // Oja update
    oja_kernel<<<B * H, 128>>>(kvbP, W, out);
}